// round 14
// baseline (speedup 1.0000x reference)
#include <cuda_runtime.h>
#include <cuda_fp16.h>
#include <cstdint>

// Problem constants
#define BB   2
#define SS   2048
#define DIM  512
#define NH   8
#define HD   64
#define QK   512          // NH*HD
#define ROWQ 1536         // 2*QK + DIM
#define NP   4096         // B*S positions

// ---------------- scratch ----------------
__device__ float    g_qkv[NP * ROWQ];        // gemm1 output (q,k f32; v region unused)
__device__ unsigned short g_qh[NP * QK];     // Q fp16, A-frag order per (b,h)
__device__ unsigned short g_kh[NP * QK];     // K fp16, paired-B-frag order, COMPACTED
__device__ unsigned short g_vh[NP * QK];     // V fp16, paired-B-frag order, COMPACTED
__device__ uint32_t g_xaf[NP * DIM / 2];     // x fp16 A-frag words
__device__ uint32_t g_wtbf[ROWQ * DIM / 2];  // W_trans fp16 paired-B-frag words
__device__ uint32_t g_wobf[DIM * DIM / 2];   // W_o fp16 paired-B-frag words
__device__ uint32_t g_attaf[NP * DIM / 2];   // attention out fp16 A-frag words
__device__ float    g_mask[NP];              // f32 mask
__device__ int      g_cidx[NP];              // compacted key index (valid where mask!=0)
__device__ int      g_nkeys[BB];             // live keys per batch

// half2 constants
#define H2_ONE  0x3C003C00u
#define H2_C8   0x30003000u   // 1/8
#define H2_C128 0x20002000u   // 1/128

// ---------------- helpers ----------------
__device__ __forceinline__ uint32_t pack_h2(float lo, float hi) {
    uint32_t r;
    asm("cvt.rn.f16x2.f32 %0, %1, %2;" : "=r"(r) : "f"(hi), "f"(lo));
    return r;
}
__device__ __forceinline__ unsigned short f2h(float f) {
    return __half_as_ushort(__float2half_rn(f));
}
__device__ __forceinline__ uint32_t hfma2(uint32_t a, uint32_t b, uint32_t c) {
    uint32_t d;
    asm("fma.rn.f16x2 %0, %1, %2, %3;" : "=r"(d) : "r"(a), "r"(b), "r"(c));
    return d;
}
__device__ __forceinline__ uint32_t smem_u32(const void* p) {
    uint32_t a;
    asm("{ .reg .u64 t; cvta.to.shared.u64 t, %1; cvt.u32.u64 %0, t; }" : "=r"(a) : "l"(p));
    return a;
}
__device__ __forceinline__ void cp16(uint32_t dst, const void* src) {
    asm volatile("cp.async.ca.shared.global [%0], [%1], 16;" :: "r"(dst), "l"(src) : "memory");
}
#define CP_COMMIT() asm volatile("cp.async.commit_group;" ::: "memory")
#define CP_WAIT0()  asm volatile("cp.async.wait_group 0;" ::: "memory")
#define CP_WAIT1()  asm volatile("cp.async.wait_group 1;" ::: "memory")

__device__ __forceinline__ void mma_f16(float* c,
    uint32_t a0, uint32_t a1, uint32_t a2, uint32_t a3, uint32_t b0, uint32_t b1)
{
    asm volatile(
        "mma.sync.aligned.m16n8k16.row.col.f32.f16.f16.f32 "
        "{%0,%1,%2,%3}, {%4,%5,%6,%7}, {%8,%9}, {%0,%1,%2,%3};"
        : "+f"(c[0]), "+f"(c[1]), "+f"(c[2]), "+f"(c[3])
        : "r"(a0), "r"(a1), "r"(a2), "r"(a3), "r"(b0), "r"(b1));
}

// half-index helpers (paired-B layouts)
__device__ __forceinline__ size_t qh_off(int bh, int s, int d) {
    int lane = 4 * (s & 7) + ((d & 7) >> 1);
    int j = ((s >> 3) & 1) + 2 * ((d >> 3) & 1);
    return (((size_t)bh * 128 + (s >> 4)) * 4 + (d >> 4)) * 256 + lane * 8 + j * 2 + (d & 1);
}
__device__ __forceinline__ size_t kh_off(int bh, int key, int d) {
    int g64 = key >> 6, n8 = (key >> 3) & 7;
    int lane = 4 * (key & 7) + ((d & 7) >> 1);
    return ((((size_t)bh * 32 + g64) * 4 + (n8 >> 1)) * 4 + (d >> 4)) * 256
           + lane * 8 + (n8 & 1) * 4 + ((d >> 3) & 1) * 2 + (d & 1);
}
__device__ __forceinline__ size_t vh_off(int bh, int key, int d) {
    int g64 = key >> 6, kk = key & 15, kb = (key >> 4) & 3;
    int lane = 4 * (d & 7) + ((kk & 7) >> 1);
    return ((((size_t)bh * 32 + g64) * 4 + (d >> 4)) * 4 + kb) * 256
           + lane * 8 + ((d >> 3) & 1) * 4 + ((kk >> 3) & 1) * 2 + (kk & 1);
}

// ---------------- fused prep ----------------
__device__ __forceinline__ void emit_af(const float4* __restrict__ src,
                                        uint32_t* __restrict__ dst, int i) {
    float4 v = src[i];
    int r = i >> 7, c0 = (i & 127) * 4;
    int rm = r & 15;
    size_t block = (size_t)(r >> 4) * 32 + (c0 >> 4);
    int lane = 4 * (rm & 7) + ((c0 & 7) >> 1);
    int j = (rm >> 3) + 2 * ((c0 >> 3) & 1);
    dst[block * 128 + lane * 4 + j]       = pack_h2(v.x, v.y);
    dst[block * 128 + (lane + 1) * 4 + j] = pack_h2(v.z, v.w);
}
__device__ __forceinline__ void emit_bf2(const float4* __restrict__ src,
                                         uint32_t* __restrict__ dst, int i) {
    float4 v = src[i];
    int r = i >> 7, c0 = (i & 127) * 4;
    size_t block = (size_t)(r >> 4) * 32 + (c0 >> 4);
    int lane = 4 * (r & 7) + ((c0 & 7) >> 1);
    int w0 = ((r >> 3) & 1) * 2 + ((c0 >> 3) & 1);
    dst[block * 128 + lane * 4 + w0]       = pack_h2(v.x, v.y);
    dst[block * 128 + (lane + 1) * 4 + w0] = pack_h2(v.z, v.w);
}

__global__ void prep_kernel(const float4* __restrict__ x,
                            const unsigned char* __restrict__ mraw,
                            const float4* __restrict__ Wt,
                            const float4* __restrict__ Wo)
{
    const int blk = blockIdx.x, tid = threadIdx.x;
    if (blk < 2048) {
        emit_af(x, g_xaf, blk * 256 + tid);
    } else if (blk < 2816) {
        emit_bf2(Wt, g_wtbf, (blk - 2048) * 256 + tid);
    } else if (blk < 3072) {
        emit_bf2(Wo, g_wobf, (blk - 2816) * 256 + tid);
    } else {
        const int bb = blk - 3072;
        __shared__ int typ_s;
        __shared__ int wsum[8];
        if (tid == 0) {
            int t = 1;
            for (int i = 0; i < 512; i++) {
                unsigned char c = mraw[i];
                if ((i & 3) != 0 && c != 0) { t = (c == 0x3f || c == 0x80) ? 2 : 0; break; }
            }
            typ_s = t;
        }
        __syncthreads();
        const int t = typ_s;
        const int base = bb * SS;
        const int p0 = tid * 8;
        float mv[8];
        int cnt = 0;
#pragma unroll
        for (int i = 0; i < 8; i++) {
            int p = base + p0 + i;
            float m;
            if (t == 0)      m = mraw[p] ? 1.0f : 0.0f;
            else if (t == 1) m = (((const int*)mraw)[p] != 0) ? 1.0f : 0.0f;
            else             m = (((const float*)mraw)[p] != 0.0f) ? 1.0f : 0.0f;
            mv[i] = m;
            cnt += (m != 0.0f);
        }
        const int lane = tid & 31, wid = tid >> 5;
        int xs = cnt;
#pragma unroll
        for (int o = 1; o < 32; o <<= 1) {
            int y = __shfl_up_sync(0xffffffffu, xs, o);
            if (lane >= o) xs += y;
        }
        if (lane == 31) wsum[wid] = xs;
        __syncthreads();
        if (tid == 0) {
            int a = 0;
#pragma unroll
            for (int ww = 0; ww < 8; ww++) { int tt = wsum[ww]; wsum[ww] = a; a += tt; }
            g_nkeys[bb] = a;
        }
        __syncthreads();
        int c = xs - cnt + wsum[wid];
#pragma unroll
        for (int i = 0; i < 8; i++) {
            int p = base + p0 + i;
            g_mask[p] = mv[i];
            if (mv[i] != 0.0f) g_cidx[p] = c++;
        }
    }
}

// ---------------- fp16 frag GEMM, BK=64, M64 tiles, fused epilogue ----------
// MODE 0: plain f32 C.  MODE 1 (gemm1): q cols -> f32 (+qh if unmasked),
// k cols -> f32, v cols -> vh fp16 at compacted index if masked (no f32).
template<int MB, int MODE>
__global__ void __launch_bounds__(256, 2) gemm_af_kernel(
    const uint32_t* __restrict__ Aaf, const uint32_t* __restrict__ Bbf,
    float* __restrict__ C, int M, int N, int K)
{
    constexpr int MF  = MB / 2;
    constexpr int ACH = MB * 128;
    constexpr int TCH = ACH + 1024;
    constexpr int SWORDS = TCH * 4;

    extern __shared__ uint32_t gsm[];
    const uint32_t sbase = smem_u32(gsm);

    const int tid = threadIdx.x;
    const int w = tid >> 5, lane = tid & 31;
    const int g = lane >> 2, t = lane & 3;
    const int wm = w >> 2, wn = w & 3;
    const int bm = blockIdx.y, bn = blockIdx.x;
    const int K16 = K >> 4;
    const int nst = K >> 6;

    const char* Ab = (const char*)Aaf;
    const char* Bb = (const char*)Bbf;

    auto issue = [&](int s) {
        uint32_t base = sbase + (uint32_t)((s % 3) * (SWORDS * 4));
#pragma unroll
        for (int c = 0; c < TCH / 256; c++) {
            int ch = tid + 256 * c;
            if (ch < ACH) {
                int ablk = ch >> 5;
                cp16(base + (uint32_t)(ch * 16),
                     Ab + ((size_t)((bm * MB + (ablk >> 2)) * K16 + s * 4 + (ablk & 3))) * 512 + (ch & 31) * 16);
            } else {
                int ch2 = ch - ACH;
                int bblk = ch2 >> 5;
                cp16(base + (uint32_t)(ch * 16),
                     Bb + ((size_t)((bn * 8 + (bblk >> 2)) * K16 + s * 4 + (bblk & 3))) * 512 + (ch2 & 31) * 16);
            }
        }
        CP_COMMIT();
    };

    float acc[MF][4][4];
#pragma unroll
    for (int mf = 0; mf < MF; mf++)
#pragma unroll
        for (int nf = 0; nf < 4; nf++)
#pragma unroll
            for (int c = 0; c < 4; c++) acc[mf][nf][c] = 0.0f;

    issue(0);
    issue(1);

    for (int s = 0; s < nst; s++) {
        if (s + 1 == nst) { CP_WAIT0(); } else { CP_WAIT1(); }
        __syncthreads();
        if (s + 2 < nst) issue(s + 2);

        uint32_t* As = gsm + (s % 3) * SWORDS;
        uint32_t* Bs = As + ACH * 4;

#pragma unroll
        for (int kb = 0; kb < 4; kb++) {
            uint32_t a[MF][4];
#pragma unroll
            for (int mf = 0; mf < MF; mf++) {
                int mb = wm * MF + mf;
                uint4 av = *(const uint4*)&As[(mb * 4 + kb) * 128 + 4 * lane];
                a[mf][0] = av.x; a[mf][1] = av.y; a[mf][2] = av.z; a[mf][3] = av.w;
            }
#pragma unroll
            for (int nfp = 0; nfp < 2; nfp++) {
                uint4 bv = *(const uint4*)&Bs[((wn * 2 + nfp) * 4 + kb) * 128 + 4 * lane];
#pragma unroll
                for (int mf = 0; mf < MF; mf++) {
                    mma_f16(acc[mf][2 * nfp],     a[mf][0], a[mf][1], a[mf][2], a[mf][3], bv.x, bv.y);
                    mma_f16(acc[mf][2 * nfp + 1], a[mf][0], a[mf][1], a[mf][2], a[mf][3], bv.z, bv.w);
                }
            }
        }
    }

    if (MODE == 0) {
#pragma unroll
        for (int mf = 0; mf < MF; mf++) {
            int row = bm * (MB * 16) + wm * (MF * 16) + mf * 16 + g;
#pragma unroll
            for (int nf = 0; nf < 4; nf++) {
                int col = bn * 128 + wn * 32 + nf * 8 + 2 * t;
                *(float2*)&C[(size_t)row * N + col]       = make_float2(acc[mf][nf][0], acc[mf][nf][1]);
                *(float2*)&C[(size_t)(row + 8) * N + col] = make_float2(acc[mf][nf][2], acc[mf][nf][3]);
            }
        }
    } else {
#pragma unroll
        for (int mf = 0; mf < MF; mf++) {
            int row0 = bm * (MB * 16) + wm * (MF * 16) + mf * 16 + g;
#pragma unroll
            for (int rr = 0; rr < 2; rr++) {
                int row = row0 + rr * 8;
                int bb = row >> 11, s = row & 2047;
                float m = g_mask[row];
                if (bn < 8) {
                    // q/k: f32 store (rotate consumes masked rows)
#pragma unroll
                    for (int nf = 0; nf < 4; nf++) {
                        int col = bn * 128 + wn * 32 + nf * 8 + 2 * t;
                        *(float2*)&C[(size_t)row * N + col] =
                            make_float2(acc[mf][nf][2 * rr], acc[mf][nf][2 * rr + 1]);
                    }
                    if (bn < 4 && m == 0.0f) {
                        // unmasked q: emit fp16 directly (rotation is identity)
#pragma unroll
                        for (int nf = 0; nf < 4; nf++) {
                            int col = bn * 128 + wn * 32 + nf * 8 + 2 * t;
                            g_qh[qh_off(bb * 8 + (col >> 6), s, col & 63)] =
                                f2h(acc[mf][nf][2 * rr]);
                            g_qh[qh_off(bb * 8 + (col >> 6), s, (col + 1) & 63)] =
                                f2h(acc[mf][nf][2 * rr + 1]);
                        }
                    }
                } else {
                    // v: fp16 at compacted key index (masked rows only), no f32
                    if (m != 0.0f) {
                        int c = g_cidx[row];
#pragma unroll
                        for (int nf = 0; nf < 4; nf++) {
                            int col = bn * 128 + wn * 32 + nf * 8 + 2 * t - 1024;
                            g_vh[vh_off(bb * 8 + (col >> 6), c, col & 63)] =
                                f2h(acc[mf][nf][2 * rr]);
                            g_vh[vh_off(bb * 8 + (col >> 6), c, (col + 1) & 63)] =
                                f2h(acc[mf][nf][2 * rr + 1]);
                        }
                    }
                }
            }
        }
    }
}

// ---------------- rotation (masked rows only; q,k) ---------------------------
__global__ void __launch_bounds__(256) rotate_kernel(const float* __restrict__ rot)
{
    const int p = blockIdx.x, tid = threadIdx.x;
    if (g_mask[p] == 0.0f) return;           // uniform per block

    const int b = p >> 11, s = p & 2047;
    const int c = g_cidx[p];
    const float* row = &g_qkv[(size_t)p * ROWQ];

    __shared__ float4 Rr[64 * 17];
    __shared__ float4 X4[256];

    const uint32_t rbase = smem_u32(Rr);
    const uint32_t xbase = smem_u32(X4);
    const float4* R4 = (const float4*)(rot + (size_t)p * 4096);
#pragma unroll
    for (int t2 = 0; t2 < 4; t2++) {
        int idx4 = tid + 256 * t2;
        cp16(rbase + (uint32_t)(((idx4 >> 4) * 17 + (idx4 & 15)) * 16), R4 + idx4);
    }
    cp16(xbase + (uint32_t)(tid * 16), ((const float4*)row) + tid);
    CP_COMMIT();
    CP_WAIT0();
    __syncthreads();

    const int i  = tid & 63;
    const int vb = tid >> 6;
    float acc[4] = {0.0f, 0.0f, 0.0f, 0.0f};
#pragma unroll
    for (int j4 = 0; j4 < 16; j4++) {
        float4 r = Rr[i * 17 + j4];
#pragma unroll
        for (int ii = 0; ii < 4; ii++) {
            float4 xv = X4[(vb + 4 * ii) * 16 + j4];
            acc[ii] = fmaf(r.x, xv.x, acc[ii]);
            acc[ii] = fmaf(r.y, xv.y, acc[ii]);
            acc[ii] = fmaf(r.z, xv.z, acc[ii]);
            acc[ii] = fmaf(r.w, xv.w, acc[ii]);
        }
    }
#pragma unroll
    for (int ii = 0; ii < 4; ii++) {
        int vv = vb + 4 * ii;
        unsigned short hv = f2h(acc[ii]);
        if (vv < 8) g_qh[qh_off(b * 8 + vv, s, i)] = hv;
        else        g_kh[kh_off(b * 8 + vv - 8, c, i)] = hv;
    }
}

// ---------------- fp16 mma.sync Taylor attention (paired-B K/V) --------------
#define STGW 8192   // stage words: K 16KB | V 16KB

__global__ void __launch_bounds__(256, 2) attn_mma_kernel(uint32_t* __restrict__ outaf)
{
    extern __shared__ uint32_t sm[];
    const uint32_t sbase = smem_u32(sm);

    const int tid = threadIdx.x;
    const int w = tid >> 5, lane = tid & 31;
    const int t = lane & 3;
    const int qt = blockIdx.x, bh = blockIdx.y;
    const int b = bh >> 3, h = bh & 7;
    const int N = g_nkeys[b];
    const int nst = (N + 127) >> 7;

    uint32_t qa[4][4];
    {
        int qblk = qt * 8 + w;
        const uint4* qp = reinterpret_cast<const uint4*>(g_qh)
                          + (((size_t)bh * 128 + qblk) * 4) * 32 + lane;
#pragma unroll
        for (int k16 = 0; k16 < 4; k16++) {
            uint4 v = qp[k16 * 32];
            qa[k16][0] = v.x; qa[k16][1] = v.y; qa[k16][2] = v.z; qa[k16][3] = v.w;
        }
    }

    const char* kbase = (const char*)(g_kh + (size_t)bh * 32 * 4096);
    const char* vbase = (const char*)(g_vh + (size_t)bh * 32 * 4096);

    auto issue_stage = [&](int s) {
        const uint32_t dstb = sbase + (uint32_t)((s & 1) * STGW * 4);
        const char* ks = kbase + (size_t)s * 16384;
        const char* vs = vbase + (size_t)s * 16384;
#pragma unroll
        for (int c = 0; c < 4; c++) {
            int ch = tid * 4 + c;
            cp16(dstb + (uint32_t)(ch * 16), ks + ch * 16);
            cp16(dstb + 16384u + (uint32_t)(ch * 16), vs + ch * 16);
        }
        CP_COMMIT();
    };

    float outr[8][4];
#pragma unroll
    for (int n = 0; n < 8; n++)
#pragma unroll
        for (int j = 0; j < 4; j++) outr[n][j] = 0.0f;
    float dacc[4] = {0.0f, 0.0f, 0.0f, 0.0f};

    issue_stage(0);

    for (int s = 0; s < nst; s++) {
        CP_WAIT0();
        __syncthreads();
        if (s + 1 < nst) issue_stage(s + 1);

        uint32_t* base = sm + (s & 1) * STGW;
        const bool needmask = ((s + 1) * 128 > N);

#pragma unroll
        for (int h2 = 0; h2 < 2; h2++) {
            uint32_t* Kf = base + h2 * 2048;
            uint32_t* Vf = base + 4096 + h2 * 2048;

            float sc[8][4];
#pragma unroll
            for (int n = 0; n < 8; n++)
#pragma unroll
                for (int j = 0; j < 4; j++) sc[n][j] = 0.0f;

#pragma unroll
            for (int k16 = 0; k16 < 4; k16++) {
#pragma unroll
                for (int pr = 0; pr < 4; pr++) {
                    uint4 kf = *(const uint4*)&Kf[(pr * 4 + k16) * 128 + 4 * lane];
                    mma_f16(sc[2 * pr],     qa[k16][0], qa[k16][1], qa[k16][2], qa[k16][3], kf.x, kf.y);
                    mma_f16(sc[2 * pr + 1], qa[k16][0], qa[k16][1], qa[k16][2], qa[k16][3], kf.z, kf.w);
                }
            }

            uint32_t wpA[8], wpB[8];
#pragma unroll
            for (int n = 0; n < 8; n++) {
                uint32_t sA = pack_h2(sc[n][0], sc[n][1]);
                uint32_t sB = pack_h2(sc[n][2], sc[n][3]);
                wpA[n] = hfma2(sA, hfma2(sA, H2_C128, H2_C8), H2_ONE);
                wpB[n] = hfma2(sB, hfma2(sB, H2_C128, H2_C8), H2_ONE);
                if (needmask) {
                    int k0 = s * 128 + h2 * 64 + n * 8 + 2 * t;
                    uint32_t mm = (k0 < N ? 0x0000FFFFu : 0u) | (k0 + 1 < N ? 0xFFFF0000u : 0u);
                    wpA[n] &= mm;
                    wpB[n] &= mm;
                }
            }

#pragma unroll
            for (int j2 = 0; j2 < 4; j2++) {
                uint32_t a0 = wpA[2 * j2], a1 = wpB[2 * j2];
                uint32_t a2 = wpA[2 * j2 + 1], a3 = wpB[2 * j2 + 1];
                mma_f16(dacc, a0, a1, a2, a3, H2_ONE, H2_ONE);
#pragma unroll
                for (int dp = 0; dp < 4; dp++) {
                    uint4 vf = *(const uint4*)&Vf[(dp * 4 + j2) * 128 + 4 * lane];
                    mma_f16(outr[2 * dp],     a0, a1, a2, a3, vf.x, vf.y);
                    mma_f16(outr[2 * dp + 1], a0, a1, a2, a3, vf.z, vf.w);
                }
            }
        }
    }

    float inv0 = 1.0f / dacc[0];
    float inv1 = 1.0f / dacc[2];

    {
        size_t qb = (size_t)((b * SS + qt * 128 + w * 16) >> 4);
#pragma unroll
        for (int dn = 0; dn < 8; dn++) {
            size_t block = qb * 32 + h * 4 + (dn >> 1);
            int jA = 2 * (dn & 1);
            outaf[block * 128 + lane * 4 + jA]     = pack_h2(outr[dn][0] * inv0, outr[dn][1] * inv0);
            outaf[block * 128 + lane * 4 + jA + 1] = pack_h2(outr[dn][2] * inv1, outr[dn][3] * inv1);
        }
    }
}

// ---------------- launch ----------------
extern "C" void kernel_launch(void* const* d_in, const int* in_sizes, int n_in,
                              void* d_out, int out_size)
{
    const float*         x    = (const float*)d_in[0];
    const unsigned char* mask = (const unsigned char*)d_in[1];
    const float*         rot  = (const float*)d_in[2];
    const float*         Wt   = (const float*)d_in[3];
    const float*         Wo   = (const float*)d_in[4];
    float*               out  = (float*)d_out;

    float *qkv_p;
    uint32_t *attaf_p, *xaf_p, *wtbf_p, *wobf_p;
    cudaGetSymbolAddress((void**)&qkv_p,   g_qkv);
    cudaGetSymbolAddress((void**)&attaf_p, g_attaf);
    cudaGetSymbolAddress((void**)&xaf_p,   g_xaf);
    cudaGetSymbolAddress((void**)&wtbf_p,  g_wtbf);
    cudaGetSymbolAddress((void**)&wobf_p,  g_wobf);

    static const int ATT_SMEM  = 2 * STGW * 4;               // 65,536 B
    static const int GEMM_SMEM = 3 * (4 * 128 + 1024) * 16;  // 73,728 B
    cudaFuncSetAttribute(attn_mma_kernel, cudaFuncAttributeMaxDynamicSharedMemorySize, ATT_SMEM);
    cudaFuncSetAttribute(gemm_af_kernel<4, 1>, cudaFuncAttributeMaxDynamicSharedMemorySize, GEMM_SMEM);
    cudaFuncSetAttribute(gemm_af_kernel<4, 0>, cudaFuncAttributeMaxDynamicSharedMemorySize, GEMM_SMEM);

    // fused prep (must precede gemm1: mask/cidx used in its epilogue)
    prep_kernel<<<3074, 256>>>((const float4*)x, mask, (const float4*)Wt, (const float4*)Wo);

    // qkv = x @ W_trans^T ; fused epilogue emits unmasked q fp16 + compacted v fp16
    gemm_af_kernel<4, 1><<<dim3(ROWQ / 128, NP / 64), 256, GEMM_SMEM>>>(xaf_p, wtbf_p, qkv_p, NP, ROWQ, DIM);

    // rotate masked rows' q,k -> fp16 frag layouts (compacted k)
    rotate_kernel<<<NP, 256>>>(rot);

    // attention over compacted keys -> g_attaf
    attn_mma_kernel<<<dim3(SS / 128, BB * NH), 256, ATT_SMEM>>>(attaf_p);

    // out = att @ W_o^T
    gemm_af_kernel<4, 0><<<dim3(DIM / 128, NP / 64), 256, GEMM_SMEM>>>(attaf_p, wobf_p, out, NP, DIM, DIM);
}

// round 15
// speedup vs baseline: 1.0669x; 1.0669x over previous
#include <cuda_runtime.h>
#include <cuda_fp16.h>
#include <cstdint>

// Problem constants
#define BB   2
#define SS   2048
#define DIM  512
#define NH   8
#define HD   64
#define QK   512          // NH*HD
#define ROWQ 1536         // 2*QK + DIM
#define NP   4096         // B*S positions

// ---------------- scratch ----------------
__device__ float    g_qkv[NP * ROWQ];        // gemm1 output, natural f32
__device__ unsigned short g_qh[NP * QK];     // Q fp16, A-frag order per (b,h)
__device__ unsigned short g_kh[NP * QK];     // K fp16, paired-B-frag order, COMPACTED
__device__ unsigned short g_vh[NP * QK];     // V fp16, paired-B-frag order, COMPACTED
__device__ uint32_t g_xaf[NP * DIM / 2];     // x fp16 A-frag words
__device__ uint32_t g_wtbf[ROWQ * DIM / 2];  // W_trans fp16 paired-B-frag words
__device__ uint32_t g_wobf[DIM * DIM / 2];   // W_o fp16 paired-B-frag words
__device__ uint32_t g_attaf[NP * DIM / 2];   // attention out fp16 A-frag words
__device__ float    g_mask[NP];              // f32 mask
__device__ int      g_cidx[NP];              // compacted key index (valid where mask!=0)
__device__ int      g_nkeys[BB];             // live keys per batch

// half2 constants
#define H2_ONE  0x3C003C00u
#define H2_C8   0x30003000u   // 1/8
#define H2_C128 0x20002000u   // 1/128

// ---------------- helpers ----------------
__device__ __forceinline__ uint32_t pack_h2(float lo, float hi) {
    uint32_t r;
    asm("cvt.rn.f16x2.f32 %0, %1, %2;" : "=r"(r) : "f"(hi), "f"(lo));
    return r;
}
__device__ __forceinline__ unsigned short f2h(float f) {
    return __half_as_ushort(__float2half_rn(f));
}
__device__ __forceinline__ uint32_t hfma2(uint32_t a, uint32_t b, uint32_t c) {
    uint32_t d;
    asm("fma.rn.f16x2 %0, %1, %2, %3;" : "=r"(d) : "r"(a), "r"(b), "r"(c));
    return d;
}
__device__ __forceinline__ uint32_t smem_u32(const void* p) {
    uint32_t a;
    asm("{ .reg .u64 t; cvta.to.shared.u64 t, %1; cvt.u32.u64 %0, t; }" : "=r"(a) : "l"(p));
    return a;
}
__device__ __forceinline__ void cp16(uint32_t dst, const void* src) {
    asm volatile("cp.async.ca.shared.global [%0], [%1], 16;" :: "r"(dst), "l"(src) : "memory");
}
#define CP_COMMIT() asm volatile("cp.async.commit_group;" ::: "memory")
#define CP_WAIT0()  asm volatile("cp.async.wait_group 0;" ::: "memory")
#define CP_WAIT1()  asm volatile("cp.async.wait_group 1;" ::: "memory")

__device__ __forceinline__ void mma_f16(float* c,
    uint32_t a0, uint32_t a1, uint32_t a2, uint32_t a3, uint32_t b0, uint32_t b1)
{
    asm volatile(
        "mma.sync.aligned.m16n8k16.row.col.f32.f16.f16.f32 "
        "{%0,%1,%2,%3}, {%4,%5,%6,%7}, {%8,%9}, {%0,%1,%2,%3};"
        : "+f"(c[0]), "+f"(c[1]), "+f"(c[2]), "+f"(c[3])
        : "r"(a0), "r"(a1), "r"(a2), "r"(a3), "r"(b0), "r"(b1));
}

// half-index helpers (paired-B layouts)
__device__ __forceinline__ size_t qh_off(int bh, int s, int d) {
    int lane = 4 * (s & 7) + ((d & 7) >> 1);
    int j = ((s >> 3) & 1) + 2 * ((d >> 3) & 1);
    return (((size_t)bh * 128 + (s >> 4)) * 4 + (d >> 4)) * 256 + lane * 8 + j * 2 + (d & 1);
}
__device__ __forceinline__ size_t kh_off(int bh, int key, int d) {
    int g64 = key >> 6, n8 = (key >> 3) & 7;
    int lane = 4 * (key & 7) + ((d & 7) >> 1);
    return ((((size_t)bh * 32 + g64) * 4 + (n8 >> 1)) * 4 + (d >> 4)) * 256
           + lane * 8 + (n8 & 1) * 4 + ((d >> 3) & 1) * 2 + (d & 1);
}
__device__ __forceinline__ size_t vh_off(int bh, int key, int d) {
    int g64 = key >> 6, kk = key & 15, kb = (key >> 4) & 3;
    int lane = 4 * (d & 7) + ((kk & 7) >> 1);
    return ((((size_t)bh * 32 + g64) * 4 + (d >> 4)) * 4 + kb) * 256
           + lane * 8 + ((d >> 3) & 1) * 4 + ((kk >> 3) & 1) * 2 + (kk & 1);
}

// ---------------- fused prep ----------------
__device__ __forceinline__ void emit_af(const float4* __restrict__ src,
                                        uint32_t* __restrict__ dst, int i) {
    float4 v = src[i];
    int r = i >> 7, c0 = (i & 127) * 4;
    int rm = r & 15;
    size_t block = (size_t)(r >> 4) * 32 + (c0 >> 4);
    int lane = 4 * (rm & 7) + ((c0 & 7) >> 1);
    int j = (rm >> 3) + 2 * ((c0 >> 3) & 1);
    dst[block * 128 + lane * 4 + j]       = pack_h2(v.x, v.y);
    dst[block * 128 + (lane + 1) * 4 + j] = pack_h2(v.z, v.w);
}
__device__ __forceinline__ void emit_bf2(const float4* __restrict__ src,
                                         uint32_t* __restrict__ dst, int i) {
    float4 v = src[i];
    int r = i >> 7, c0 = (i & 127) * 4;
    size_t block = (size_t)(r >> 4) * 32 + (c0 >> 4);
    int lane = 4 * (r & 7) + ((c0 & 7) >> 1);
    int w0 = ((r >> 3) & 1) * 2 + ((c0 >> 3) & 1);
    dst[block * 128 + lane * 4 + w0]       = pack_h2(v.x, v.y);
    dst[block * 128 + (lane + 1) * 4 + w0] = pack_h2(v.z, v.w);
}

__global__ void prep_kernel(const float4* __restrict__ x,
                            const unsigned char* __restrict__ mraw,
                            const float4* __restrict__ Wt,
                            const float4* __restrict__ Wo)
{
    const int blk = blockIdx.x, tid = threadIdx.x;
    if (blk < 2048) {
        emit_af(x, g_xaf, blk * 256 + tid);
    } else if (blk < 2816) {
        emit_bf2(Wt, g_wtbf, (blk - 2048) * 256 + tid);
    } else if (blk < 3072) {
        emit_bf2(Wo, g_wobf, (blk - 2816) * 256 + tid);
    } else {
        const int bb = blk - 3072;
        __shared__ int typ_s;
        __shared__ int wsum[8];
        if (tid == 0) {
            int t = 1;
            for (int i = 0; i < 512; i++) {
                unsigned char c = mraw[i];
                if ((i & 3) != 0 && c != 0) { t = (c == 0x3f || c == 0x80) ? 2 : 0; break; }
            }
            typ_s = t;
        }
        __syncthreads();
        const int t = typ_s;
        const int base = bb * SS;
        const int p0 = tid * 8;
        float mv[8];
        int cnt = 0;
#pragma unroll
        for (int i = 0; i < 8; i++) {
            int p = base + p0 + i;
            float m;
            if (t == 0)      m = mraw[p] ? 1.0f : 0.0f;
            else if (t == 1) m = (((const int*)mraw)[p] != 0) ? 1.0f : 0.0f;
            else             m = (((const float*)mraw)[p] != 0.0f) ? 1.0f : 0.0f;
            mv[i] = m;
            cnt += (m != 0.0f);
        }
        const int lane = tid & 31, wid = tid >> 5;
        int xs = cnt;
#pragma unroll
        for (int o = 1; o < 32; o <<= 1) {
            int y = __shfl_up_sync(0xffffffffu, xs, o);
            if (lane >= o) xs += y;
        }
        if (lane == 31) wsum[wid] = xs;
        __syncthreads();
        if (tid == 0) {
            int a = 0;
#pragma unroll
            for (int ww = 0; ww < 8; ww++) { int tt = wsum[ww]; wsum[ww] = a; a += tt; }
            g_nkeys[bb] = a;
        }
        __syncthreads();
        int c = xs - cnt + wsum[wid];
#pragma unroll
        for (int i = 0; i < 8; i++) {
            int p = base + p0 + i;
            g_mask[p] = mv[i];
            if (mv[i] != 0.0f) g_cidx[p] = c++;
        }
    }
}

// ---------------- fp16 frag GEMM, BK=64 stages, templated M-tile -------------
// MODE 0: plain f32 C stores.
// MODE 1 (gemm1): q cols (bn<4) stored always; k/v cols (bn>=4) stored only
// for masked rows (unmasked k/v are never read downstream -> dead stores).
template<int MB, int MODE>
__global__ void __launch_bounds__(256, 2) gemm_af_kernel(
    const uint32_t* __restrict__ Aaf, const uint32_t* __restrict__ Bbf,
    float* __restrict__ C, int M, int N, int K)
{
    constexpr int MF  = MB / 2;
    constexpr int ACH = MB * 128;
    constexpr int TCH = ACH + 1024;
    constexpr int SWORDS = TCH * 4;

    extern __shared__ uint32_t gsm[];
    const uint32_t sbase = smem_u32(gsm);

    const int tid = threadIdx.x;
    const int w = tid >> 5, lane = tid & 31;
    const int g = lane >> 2, t = lane & 3;
    const int wm = w >> 2, wn = w & 3;
    const int bm = blockIdx.y, bn = blockIdx.x;
    const int K16 = K >> 4;
    const int nst = K >> 6;                 // BK = 64

    const char* Ab = (const char*)Aaf;
    const char* Bb = (const char*)Bbf;

    auto issue = [&](int s) {
        uint32_t base = sbase + (uint32_t)((s % 3) * (SWORDS * 4));
#pragma unroll
        for (int c = 0; c < TCH / 256; c++) {
            int ch = tid + 256 * c;
            if (ch < ACH) {
                int ablk = ch >> 5;
                cp16(base + (uint32_t)(ch * 16),
                     Ab + ((size_t)((bm * MB + (ablk >> 2)) * K16 + s * 4 + (ablk & 3))) * 512 + (ch & 31) * 16);
            } else {
                int ch2 = ch - ACH;
                int bblk = ch2 >> 5;
                cp16(base + (uint32_t)(ch * 16),
                     Bb + ((size_t)((bn * 8 + (bblk >> 2)) * K16 + s * 4 + (bblk & 3))) * 512 + (ch2 & 31) * 16);
            }
        }
        CP_COMMIT();
    };

    float acc[MF][4][4];
#pragma unroll
    for (int mf = 0; mf < MF; mf++)
#pragma unroll
        for (int nf = 0; nf < 4; nf++)
#pragma unroll
            for (int c = 0; c < 4; c++) acc[mf][nf][c] = 0.0f;

    issue(0);
    issue(1);

    for (int s = 0; s < nst; s++) {
        if (s + 1 == nst) { CP_WAIT0(); } else { CP_WAIT1(); }
        __syncthreads();
        if (s + 2 < nst) issue(s + 2);

        uint32_t* As = gsm + (s % 3) * SWORDS;
        uint32_t* Bs = As + ACH * 4;

#pragma unroll
        for (int kb = 0; kb < 4; kb++) {
            uint32_t a[MF][4];
#pragma unroll
            for (int mf = 0; mf < MF; mf++) {
                int mb = wm * MF + mf;
                uint4 av = *(const uint4*)&As[(mb * 4 + kb) * 128 + 4 * lane];
                a[mf][0] = av.x; a[mf][1] = av.y; a[mf][2] = av.z; a[mf][3] = av.w;
            }
#pragma unroll
            for (int nfp = 0; nfp < 2; nfp++) {
                uint4 bv = *(const uint4*)&Bs[((wn * 2 + nfp) * 4 + kb) * 128 + 4 * lane];
#pragma unroll
                for (int mf = 0; mf < MF; mf++) {
                    mma_f16(acc[mf][2 * nfp],     a[mf][0], a[mf][1], a[mf][2], a[mf][3], bv.x, bv.y);
                    mma_f16(acc[mf][2 * nfp + 1], a[mf][0], a[mf][1], a[mf][2], a[mf][3], bv.z, bv.w);
                }
            }
        }
    }

    if (MODE == 0 || bn < 4) {
#pragma unroll
        for (int mf = 0; mf < MF; mf++) {
            int row = bm * (MB * 16) + wm * (MF * 16) + mf * 16 + g;
#pragma unroll
            for (int nf = 0; nf < 4; nf++) {
                int col = bn * 128 + wn * 32 + nf * 8 + 2 * t;
                *(float2*)&C[(size_t)row * N + col]       = make_float2(acc[mf][nf][0], acc[mf][nf][1]);
                *(float2*)&C[(size_t)(row + 8) * N + col] = make_float2(acc[mf][nf][2], acc[mf][nf][3]);
            }
        }
    } else {
        // gemm1 k/v columns: only masked rows are ever read by rotate
#pragma unroll
        for (int mf = 0; mf < MF; mf++) {
            int row = bm * (MB * 16) + wm * (MF * 16) + mf * 16 + g;
            bool mA = (g_mask[row] != 0.0f);
            bool mB = (g_mask[row + 8] != 0.0f);
#pragma unroll
            for (int nf = 0; nf < 4; nf++) {
                int col = bn * 128 + wn * 32 + nf * 8 + 2 * t;
                if (mA) *(float2*)&C[(size_t)row * N + col]       = make_float2(acc[mf][nf][0], acc[mf][nf][1]);
                if (mB) *(float2*)&C[(size_t)(row + 8) * N + col] = make_float2(acc[mf][nf][2], acc[mf][nf][3]);
            }
        }
    }
}

// ---------------- rotation (cp.async staging) + compacted k/v ---------------
__global__ void __launch_bounds__(256) rotate_kernel(const float* __restrict__ rot)
{
    const int p = blockIdx.x, tid = threadIdx.x;
    const int b = p >> 11, s = p & 2047;
    float* row = &g_qkv[(size_t)p * ROWQ];
    const bool masked = (g_mask[p] != 0.0f);

    if (masked) {
        const int c = g_cidx[p];
        __shared__ float4 Rr[64 * 17];   // row i at Rr[i*17 + j4]
        __shared__ float4 X4[256];

        const uint32_t rbase = smem_u32(Rr);
        const uint32_t xbase = smem_u32(X4);
        const float4* R4 = (const float4*)(rot + (size_t)p * 4096);
#pragma unroll
        for (int t2 = 0; t2 < 4; t2++) {
            int idx4 = tid + 256 * t2;
            cp16(rbase + (uint32_t)(((idx4 >> 4) * 17 + (idx4 & 15)) * 16), R4 + idx4);
        }
        cp16(xbase + (uint32_t)(tid * 16), ((const float4*)row) + tid);
        CP_COMMIT();

        // v processing overlaps the cp.async latency
#pragma unroll
        for (int t2 = 0; t2 < 2; t2++) {
            int idx = tid + 256 * t2;
            g_vh[vh_off(b * 8 + (idx >> 6), c, idx & 63)] = f2h(row[1024 + idx]);
        }

        CP_WAIT0();
        __syncthreads();

        const int i  = tid & 63;
        const int vb = tid >> 6;
        float acc[4] = {0.0f, 0.0f, 0.0f, 0.0f};
#pragma unroll
        for (int j4 = 0; j4 < 16; j4++) {
            float4 r = Rr[i * 17 + j4];
#pragma unroll
            for (int ii = 0; ii < 4; ii++) {
                float4 xv = X4[(vb + 4 * ii) * 16 + j4];
                acc[ii] = fmaf(r.x, xv.x, acc[ii]);
                acc[ii] = fmaf(r.y, xv.y, acc[ii]);
                acc[ii] = fmaf(r.z, xv.z, acc[ii]);
                acc[ii] = fmaf(r.w, xv.w, acc[ii]);
            }
        }
#pragma unroll
        for (int ii = 0; ii < 4; ii++) {
            int vv = vb + 4 * ii;
            unsigned short hv = f2h(acc[ii]);
            if (vv < 8) g_qh[qh_off(b * 8 + vv, s, i)] = hv;
            else        g_kh[kh_off(b * 8 + vv - 8, c, i)] = hv;
        }
    } else {
#pragma unroll
        for (int t2 = 0; t2 < 2; t2++) {
            int idx = tid + 256 * t2;
            g_qh[qh_off(b * 8 + (idx >> 6), s, idx & 63)] = f2h(row[idx]);
        }
    }
}

// ---------------- fp16 mma.sync Taylor attention (paired-B K/V) --------------
#define STGW 8192   // stage words: K 16KB | V 16KB

__global__ void __launch_bounds__(256, 2) attn_mma_kernel(uint32_t* __restrict__ outaf)
{
    extern __shared__ uint32_t sm[];
    const uint32_t sbase = smem_u32(sm);

    const int tid = threadIdx.x;
    const int w = tid >> 5, lane = tid & 31;
    const int t = lane & 3;
    const int qt = blockIdx.x, bh = blockIdx.y;
    const int b = bh >> 3, h = bh & 7;
    const int N = g_nkeys[b];
    const int nst = (N + 127) >> 7;

    uint32_t qa[4][4];
    {
        int qblk = qt * 8 + w;
        const uint4* qp = reinterpret_cast<const uint4*>(g_qh)
                          + (((size_t)bh * 128 + qblk) * 4) * 32 + lane;
#pragma unroll
        for (int k16 = 0; k16 < 4; k16++) {
            uint4 v = qp[k16 * 32];
            qa[k16][0] = v.x; qa[k16][1] = v.y; qa[k16][2] = v.z; qa[k16][3] = v.w;
        }
    }

    const char* kbase = (const char*)(g_kh + (size_t)bh * 32 * 4096);
    const char* vbase = (const char*)(g_vh + (size_t)bh * 32 * 4096);

    auto issue_stage = [&](int s) {
        const uint32_t dstb = sbase + (uint32_t)((s & 1) * STGW * 4);
        const char* ks = kbase + (size_t)s * 16384;
        const char* vs = vbase + (size_t)s * 16384;
#pragma unroll
        for (int c = 0; c < 4; c++) {
            int ch = tid * 4 + c;
            cp16(dstb + (uint32_t)(ch * 16), ks + ch * 16);
            cp16(dstb + 16384u + (uint32_t)(ch * 16), vs + ch * 16);
        }
        CP_COMMIT();
    };

    float outr[8][4];
#pragma unroll
    for (int n = 0; n < 8; n++)
#pragma unroll
        for (int j = 0; j < 4; j++) outr[n][j] = 0.0f;
    float dacc[4] = {0.0f, 0.0f, 0.0f, 0.0f};

    issue_stage(0);

    for (int s = 0; s < nst; s++) {
        CP_WAIT0();
        __syncthreads();
        if (s + 1 < nst) issue_stage(s + 1);

        uint32_t* base = sm + (s & 1) * STGW;
        const bool needmask = ((s + 1) * 128 > N);

#pragma unroll
        for (int h2 = 0; h2 < 2; h2++) {
            uint32_t* Kf = base + h2 * 2048;
            uint32_t* Vf = base + 4096 + h2 * 2048;

            float sc[8][4];
#pragma unroll
            for (int n = 0; n < 8; n++)
#pragma unroll
                for (int j = 0; j < 4; j++) sc[n][j] = 0.0f;

#pragma unroll
            for (int k16 = 0; k16 < 4; k16++) {
#pragma unroll
                for (int pr = 0; pr < 4; pr++) {
                    uint4 kf = *(const uint4*)&Kf[(pr * 4 + k16) * 128 + 4 * lane];
                    mma_f16(sc[2 * pr],     qa[k16][0], qa[k16][1], qa[k16][2], qa[k16][3], kf.x, kf.y);
                    mma_f16(sc[2 * pr + 1], qa[k16][0], qa[k16][1], qa[k16][2], qa[k16][3], kf.z, kf.w);
                }
            }

            uint32_t wpA[8], wpB[8];
#pragma unroll
            for (int n = 0; n < 8; n++) {
                uint32_t sA = pack_h2(sc[n][0], sc[n][1]);
                uint32_t sB = pack_h2(sc[n][2], sc[n][3]);
                wpA[n] = hfma2(sA, hfma2(sA, H2_C128, H2_C8), H2_ONE);
                wpB[n] = hfma2(sB, hfma2(sB, H2_C128, H2_C8), H2_ONE);
                if (needmask) {
                    int k0 = s * 128 + h2 * 64 + n * 8 + 2 * t;
                    uint32_t mm = (k0 < N ? 0x0000FFFFu : 0u) | (k0 + 1 < N ? 0xFFFF0000u : 0u);
                    wpA[n] &= mm;
                    wpB[n] &= mm;
                }
            }

#pragma unroll
            for (int j2 = 0; j2 < 4; j2++) {
                uint32_t a0 = wpA[2 * j2], a1 = wpB[2 * j2];
                uint32_t a2 = wpA[2 * j2 + 1], a3 = wpB[2 * j2 + 1];
                mma_f16(dacc, a0, a1, a2, a3, H2_ONE, H2_ONE);
#pragma unroll
                for (int dp = 0; dp < 4; dp++) {
                    uint4 vf = *(const uint4*)&Vf[(dp * 4 + j2) * 128 + 4 * lane];
                    mma_f16(outr[2 * dp],     a0, a1, a2, a3, vf.x, vf.y);
                    mma_f16(outr[2 * dp + 1], a0, a1, a2, a3, vf.z, vf.w);
                }
            }
        }
    }

    float inv0 = 1.0f / dacc[0];
    float inv1 = 1.0f / dacc[2];

    {
        size_t qb = (size_t)((b * SS + qt * 128 + w * 16) >> 4);
#pragma unroll
        for (int dn = 0; dn < 8; dn++) {
            size_t block = qb * 32 + h * 4 + (dn >> 1);
            int jA = 2 * (dn & 1);
            outaf[block * 128 + lane * 4 + jA]     = pack_h2(outr[dn][0] * inv0, outr[dn][1] * inv0);
            outaf[block * 128 + lane * 4 + jA + 1] = pack_h2(outr[dn][2] * inv1, outr[dn][3] * inv1);
        }
    }
}

// ---------------- launch ----------------
extern "C" void kernel_launch(void* const* d_in, const int* in_sizes, int n_in,
                              void* d_out, int out_size)
{
    const float*         x    = (const float*)d_in[0];
    const unsigned char* mask = (const unsigned char*)d_in[1];
    const float*         rot  = (const float*)d_in[2];
    const float*         Wt   = (const float*)d_in[3];
    const float*         Wo   = (const float*)d_in[4];
    float*               out  = (float*)d_out;

    float *qkv_p;
    uint32_t *attaf_p, *xaf_p, *wtbf_p, *wobf_p;
    cudaGetSymbolAddress((void**)&qkv_p,   g_qkv);
    cudaGetSymbolAddress((void**)&attaf_p, g_attaf);
    cudaGetSymbolAddress((void**)&xaf_p,   g_xaf);
    cudaGetSymbolAddress((void**)&wtbf_p,  g_wtbf);
    cudaGetSymbolAddress((void**)&wobf_p,  g_wobf);

    static const int ATT_SMEM   = 2 * STGW * 4;                // 65,536 B
    static const int GEMM1_SMEM = 3 * (8 * 128 + 1024) * 16;   // 98,304 B
    static const int GEMM2_SMEM = 3 * (4 * 128 + 1024) * 16;   // 73,728 B
    cudaFuncSetAttribute(attn_mma_kernel, cudaFuncAttributeMaxDynamicSharedMemorySize, ATT_SMEM);
    cudaFuncSetAttribute(gemm_af_kernel<8, 1>, cudaFuncAttributeMaxDynamicSharedMemorySize, GEMM1_SMEM);
    cudaFuncSetAttribute(gemm_af_kernel<4, 0>, cudaFuncAttributeMaxDynamicSharedMemorySize, GEMM2_SMEM);

    // fused prep (mask/cidx needed by gemm1 epilogue + rotate)
    prep_kernel<<<3074, 256>>>((const float4*)x, mask, (const float4*)Wt, (const float4*)Wo);

    // qkv = x @ W_trans^T  (128-row tiles, BK=64; dead k/v stores skipped)
    gemm_af_kernel<8, 1><<<dim3(ROWQ / 128, NP / 128), 256, GEMM1_SMEM>>>(xaf_p, wtbf_p, qkv_p, NP, ROWQ, DIM);

    // rotate q,k where masked; emit frag-ordered q + COMPACTED paired k/v
    rotate_kernel<<<NP, 256>>>(rot);

    // attention over compacted keys -> g_attaf
    attn_mma_kernel<<<dim3(SS / 128, BB * NH), 256, ATT_SMEM>>>(attaf_p);

    // out = att @ W_o^T  (64-row tiles, BK=64 -> 256 CTAs, 2/SM overlap)
    gemm_af_kernel<4, 0><<<dim3(DIM / 128, NP / 64), 256, GEMM2_SMEM>>>(attaf_p, wobf_p, out, NP, DIM, DIM);
}